// round 4
// baseline (speedup 1.0000x reference)
#include <cuda_runtime.h>
#include <cuda_bf16.h>
#include <math.h>
#include <stdint.h>

#define S_LEN 3136
#define E_DIM 1024
#define H_NUM 16
#define D_DIM 64
#define NTILES 25   // ceil(3136/128)

typedef __nv_bfloat16 bf16;

// ---------------------------------------------------------------------------
// Device scratch (allocation is forbidden)
// ---------------------------------------------------------------------------
__device__ float g_qkv[3][H_NUM * S_LEN * D_DIM];   // fp32 head-major q,k,v

__device__ __align__(16) bf16 g_Hhi[S_LEN * E_DIM];
__device__ __align__(16) bf16 g_Hlo[S_LEN * E_DIM];
__device__ __align__(16) bf16 g_Whi[4][E_DIM * E_DIM];
__device__ __align__(16) bf16 g_Wlo[4][E_DIM * E_DIM];
__device__ __align__(16) bf16 g_Qhi[H_NUM * S_LEN * D_DIM];
__device__ __align__(16) bf16 g_Qlo[H_NUM * S_LEN * D_DIM];
__device__ __align__(16) bf16 g_Khi[H_NUM * S_LEN * D_DIM];
__device__ __align__(16) bf16 g_Klo[H_NUM * S_LEN * D_DIM];
__device__ __align__(16) bf16 g_Vthi[H_NUM * D_DIM * S_LEN];   // [h][d][s]
__device__ __align__(16) bf16 g_Vtlo[H_NUM * D_DIM * S_LEN];
__device__ __align__(16) bf16 g_Ehi[(long)H_NUM * S_LEN * S_LEN];  // unnormalized exp
__device__ __align__(16) bf16 g_Elo[(long)H_NUM * S_LEN * S_LEN];
__device__ __align__(16) bf16 g_AOhi[S_LEN * E_DIM];
__device__ __align__(16) bf16 g_AOlo[S_LEN * E_DIM];
__device__ float g_part[NTILES * H_NUM * S_LEN];   // per-(ntile,row) partial sums
__device__ float g_isum[H_NUM * S_LEN];            // 1 / rowsum

// ---------------------------------------------------------------------------
// PTX helpers
// ---------------------------------------------------------------------------
__device__ __forceinline__ uint32_t smem_u32(const void* p) {
    uint32_t a;
    asm("{ .reg .u64 t; cvta.to.shared.u64 t, %1; cvt.u32.u64 %0, t; }" : "=r"(a) : "l"(p));
    return a;
}
__device__ __forceinline__ void cp16(uint32_t dst, const void* src, int srcsize) {
    asm volatile("cp.async.cg.shared.global [%0], [%1], 16, %2;"
                 :: "r"(dst), "l"(src), "r"(srcsize));
}
__device__ __forceinline__ void cpcommit() { asm volatile("cp.async.commit_group;"); }
template <int N> __device__ __forceinline__ void cpwait() {
    asm volatile("cp.async.wait_group %0;" :: "n"(N));
}
__device__ __forceinline__ void ldm4(uint32_t* r, uint32_t a) {
    asm volatile("ldmatrix.sync.aligned.m8n8.x4.shared.b16 {%0,%1,%2,%3}, [%4];"
                 : "=r"(r[0]), "=r"(r[1]), "=r"(r[2]), "=r"(r[3]) : "r"(a));
}
__device__ __forceinline__ void ldm2(uint32_t* r, uint32_t a) {
    asm volatile("ldmatrix.sync.aligned.m8n8.x2.shared.b16 {%0,%1}, [%2];"
                 : "=r"(r[0]), "=r"(r[1]) : "r"(a));
}
__device__ __forceinline__ void mma16816(float* d, const uint32_t* a, const uint32_t* b) {
    asm volatile("mma.sync.aligned.m16n8k16.row.col.f32.bf16.bf16.f32 "
                 "{%0,%1,%2,%3}, {%4,%5,%6,%7}, {%8,%9}, {%0,%1,%2,%3};"
                 : "+f"(d[0]), "+f"(d[1]), "+f"(d[2]), "+f"(d[3])
                 : "r"(a[0]), "r"(a[1]), "r"(a[2]), "r"(a[3]), "r"(b[0]), "r"(b[1]));
}
__device__ __forceinline__ void st_split2(bf16* hi, bf16* lo, float a, float b) {
    __nv_bfloat162 h;
    h.x = __float2bfloat16(a);
    h.y = __float2bfloat16(b);
    *(__nv_bfloat162*)hi = h;
    __nv_bfloat162 l;
    l.x = __float2bfloat16(a - __bfloat162float(h.x));
    l.y = __float2bfloat16(b - __bfloat162float(h.y));
    *(__nv_bfloat162*)lo = l;
}

// ---------------------------------------------------------------------------
// bf16x3 TN GEMM via mma.sync, 3-stage cp.async pipeline.
//   A: bf16 hi/lo rows [M, K-contig] stride aRow;  B: bf16 hi/lo rows [N, K-contig]
// EPI 0: fp32 C[z*cBatch + m*ldc + n]
// EPI 1: fp32 head-major qkv: C[(z*H + (n>>6))*S*64 + m*64 + (n&63)]
// EPI 2: PV: AO bf16 split at [m*E + z*64 + n], scaled by invsum[z*S+m]
// EPI 3: score: e=exp(v); bf16 split E at [z*S*S + m*S + n]; partial row sums
// ---------------------------------------------------------------------------
template <int N_TILE, int EPI>
__global__ void __launch_bounds__(256, 1) mma_gemm(
    const bf16* __restrict__ Ahi, const bf16* __restrict__ Alo, long aRow, long aBatch,
    const bf16* __restrict__ Bhi, const bf16* __restrict__ Blo, long bRow, long bBatch,
    float* __restrict__ C, long ldc, long cBatch,
    bf16* __restrict__ Dhi, bf16* __restrict__ Dlo,
    const float* __restrict__ invsum, float* __restrict__ part,
    int kChunks, int M_valid, int N_valid) {

    constexpr int AST = 80;                 // smem bytes per 32-bf16 row (64 + 16 pad)
    constexpr int A_BYTES = 128 * AST;
    constexpr int B_BYTES = N_TILE * AST;
    constexpr int STAGE = 2 * A_BYTES + 2 * B_BYTES;

    extern __shared__ char smem[];
    const uint32_t sb = smem_u32(smem);
    __shared__ float s_red[128];

    const int tid = threadIdx.x;
    const int wid = tid >> 5, lane = tid & 31;
    constexpr int WC = (N_TILE == 128) ? 4 : 2;
    constexpr int WM = (N_TILE == 128) ? 64 : 32;
    constexpr int WN = 32;
    constexpr int MI = WM / 16, NI = WN / 8;
    const int warpM = (wid / WC) * WM;
    const int warpN = (wid % WC) * WN;

    const int mBase = blockIdx.y * 128;
    const int nBase = blockIdx.x * N_TILE;
    const int z = blockIdx.z;
    Ahi += aBatch * z; Alo += aBatch * z;
    Bhi += bBatch * z; Blo += bBatch * z;

    float acc[MI][NI][4];
#pragma unroll
    for (int i = 0; i < MI; i++)
#pragma unroll
        for (int j = 0; j < NI; j++)
#pragma unroll
            for (int q = 0; q < 4; q++) acc[i][j][q] = 0.0f;

    auto issue_loads = [&](int c) {
        const long k0 = (long)c * 32;
        const uint32_t st = sb + (c % 3) * STAGE;
        for (int i = tid; i < 512; i += 256) {
            const int r = i >> 2, u = i & 3;
            const int row = mBase + r;
            const int ok = (row < M_valid) ? 16 : 0;
            const long srow = (row < M_valid) ? row : (M_valid - 1);
            const long off = srow * aRow + k0 + u * 8;
            const uint32_t dst = st + r * AST + u * 16;
            cp16(dst, Ahi + off, ok);
            cp16(dst + A_BYTES, Alo + off, ok);
        }
        for (int i = tid; i < N_TILE * 4; i += 256) {
            const int r = i >> 2, u = i & 3;
            const int row = nBase + r;
            const int ok = (row < N_valid) ? 16 : 0;
            const long srow = (row < N_valid) ? row : (N_valid - 1);
            const long off = srow * bRow + k0 + u * 8;
            const uint32_t dst = st + 2 * A_BYTES + r * AST + u * 16;
            cp16(dst, Bhi + off, ok);
            cp16(dst + B_BYTES, Blo + off, ok);
        }
        cpcommit();
    };

    issue_loads(0);
    if (kChunks > 1) issue_loads(1); else cpcommit();

    for (int c = 0; c < kChunks; c++) {
        if (c + 2 < kChunks) issue_loads(c + 2); else cpcommit();
        cpwait<2>();
        __syncthreads();

        const uint32_t st = sb + (c % 3) * STAGE;
        const uint32_t aH = st, aL = st + A_BYTES;
        const uint32_t bH = st + 2 * A_BYTES, bL = bH + B_BYTES;

#pragma unroll
        for (int s = 0; s < 2; s++) {
            uint32_t aHf[MI][4], aLf[MI][4], bHf[NI][2], bLf[NI][2];
            const int arow = warpM + (lane & 15);
            const uint32_t acol = s * 32 + (lane >> 4) * 16;
#pragma unroll
            for (int mi = 0; mi < MI; mi++) {
                const uint32_t ao = (uint32_t)((arow + mi * 16) * AST) + acol;
                ldm4(aHf[mi], aH + ao);
                ldm4(aLf[mi], aL + ao);
            }
            const int l16 = lane & 15;
            const int brow = warpN + (l16 & 7);
            const uint32_t bcol = s * 32 + (l16 >> 3) * 16;
#pragma unroll
            for (int ni = 0; ni < NI; ni++) {
                const uint32_t bo = (uint32_t)((brow + ni * 8) * AST) + bcol;
                ldm2(bHf[ni], bH + bo);
                ldm2(bLf[ni], bL + bo);
            }
#pragma unroll
            for (int mi = 0; mi < MI; mi++)
#pragma unroll
                for (int ni = 0; ni < NI; ni++) {
                    mma16816(acc[mi][ni], aHf[mi], bHf[ni]);
                    mma16816(acc[mi][ni], aHf[mi], bLf[ni]);
                    mma16816(acc[mi][ni], aLf[mi], bHf[ni]);
                }
        }
        __syncthreads();
    }

    if (EPI == 3) {
        for (int i = tid; i < 128; i += 256) s_red[i] = 0.0f;
        __syncthreads();
    }

    // epilogue
#pragma unroll
    for (int mi = 0; mi < MI; mi++) {
#pragma unroll
        for (int ni = 0; ni < NI; ni++) {
            const int rl0 = warpM + mi * 16 + (lane >> 2);
            const int col0 = nBase + warpN + ni * 8 + (lane & 3) * 2;
#pragma unroll
            for (int h = 0; h < 2; h++) {
                const int rl = rl0 + h * 8;
                const int row = mBase + rl;
                if (row >= M_valid) continue;
                const float v0 = acc[mi][ni][h * 2 + 0];
                const float v1 = acc[mi][ni][h * 2 + 1];
                if (EPI == 0) {
                    if (col0 < N_valid) {
                        C[(long)z * cBatch + (long)row * ldc + col0] = v0;
                        C[(long)z * cBatch + (long)row * ldc + col0 + 1] = v1;
                    }
                } else if (EPI == 1) {
                    const long o0 = ((long)z * H_NUM + (col0 >> 6)) * S_LEN * 64 + (long)row * 64 + (col0 & 63);
                    C[o0] = v0;
                    C[o0 + 1] = v1;
                } else if (EPI == 2) {
                    const float sc = invsum[(long)z * S_LEN + row];
                    const long o = (long)row * E_DIM + (long)z * 64 + col0;
                    st_split2(Dhi + o, Dlo + o, v0 * sc, v1 * sc);
                } else {
                    float e0 = 0.f, e1 = 0.f;
                    if (col0 < N_valid) {
                        e0 = __expf(v0);
                        e1 = __expf(v1);
                        const long o = (long)z * S_LEN * S_LEN + (long)row * S_LEN + col0;
                        st_split2(Dhi + o, Dlo + o, e0, e1);
                    }
                    atomicAdd(&s_red[rl], e0 + e1);
                }
            }
        }
    }

    if (EPI == 3) {
        __syncthreads();
        if (tid < 128) {
            const int row = mBase + tid;
            if (row < M_valid)
                part[(long)blockIdx.x * (H_NUM * S_LEN) + (long)z * S_LEN + row] = s_red[tid];
        }
    }
}

// ---------------------------------------------------------------------------
// Small kernels
// ---------------------------------------------------------------------------
__global__ void split_kernel(const float* __restrict__ src, bf16* __restrict__ hi,
                             bf16* __restrict__ lo, long n) {
    long i = ((long)blockIdx.x * blockDim.x + threadIdx.x) * 4;
    if (i >= n) return;
    float4 v = *(const float4*)(src + i);
    float f[4] = {v.x, v.y, v.z, v.w};
#pragma unroll
    for (int j = 0; j < 4; j++) {
        bf16 h = __float2bfloat16(f[j]);
        hi[i + j] = h;
        lo[i + j] = __float2bfloat16(f[j] - __bfloat162float(h));
    }
}

__global__ void rope_split_kernel(const float* __restrict__ Q, const float* __restrict__ K,
                                  const float* __restrict__ cosp, const float* __restrict__ sinp) {
    const long total = (long)H_NUM * S_LEN * 32;
    long idx = (long)blockIdx.x * blockDim.x + threadIdx.x;
    if (idx >= total) return;
    const int d = (int)(idx & 31);
    const long hs = idx >> 5;
    const int s = (int)(hs % S_LEN);
    const long base = hs << 6;

    const float c1 = cosp[s * 64 + d], s1 = sinp[s * 64 + d];
    const float c2 = cosp[s * 64 + d + 32], s2 = sinp[s * 64 + d + 32];

    float q1 = Q[base + d], q2 = Q[base + d + 32];
    float qa = (q1 * c1 - q2 * s1) * 0.125f;
    float qb = (q2 * c2 + q1 * s2) * 0.125f;
    float k1 = K[base + d], k2 = K[base + d + 32];
    float ka = k1 * c1 - k2 * s1;
    float kb = k2 * c2 + k1 * s2;

    bf16 h;
    h = __float2bfloat16(qa); g_Qhi[base + d] = h; g_Qlo[base + d] = __float2bfloat16(qa - __bfloat162float(h));
    h = __float2bfloat16(qb); g_Qhi[base + d + 32] = h; g_Qlo[base + d + 32] = __float2bfloat16(qb - __bfloat162float(h));
    h = __float2bfloat16(ka); g_Khi[base + d] = h; g_Klo[base + d] = __float2bfloat16(ka - __bfloat162float(h));
    h = __float2bfloat16(kb); g_Khi[base + d + 32] = h; g_Klo[base + d + 32] = __float2bfloat16(kb - __bfloat162float(h));
}

__global__ void vtrans_kernel(const float* __restrict__ V) {
    __shared__ float tile[64][65];
    const int h = blockIdx.z;
    const int s0 = blockIdx.x * 64;
    const int t = threadIdx.x;
    for (int i = t; i < 4096; i += 256) {
        int s = i >> 6, d = i & 63;
        tile[s][d] = V[((long)h * S_LEN + s0 + s) * 64 + d];
    }
    __syncthreads();
    for (int i = t; i < 4096; i += 256) {
        int d = i >> 6, s = i & 63;
        float v = tile[s][d];
        bf16 hi = __float2bfloat16(v);
        long o = ((long)h * 64 + d) * S_LEN + s0 + s;
        g_Vthi[o] = hi;
        g_Vtlo[o] = __float2bfloat16(v - __bfloat162float(hi));
    }
}

__global__ void reduce_rowsum_kernel() {
    int i = blockIdx.x * blockDim.x + threadIdx.x;
    if (i >= H_NUM * S_LEN) return;
    float s = 0.f;
#pragma unroll
    for (int t = 0; t < NTILES; t++) s += g_part[t * (H_NUM * S_LEN) + i];
    g_isum[i] = 1.0f / s;
}

// one block per attention row: attn_w = (Ehi + Elo) * invsum
__global__ void normalize_kernel(float* __restrict__ W) {
    const long row = blockIdx.x;
    const float inv = g_isum[row];
    const bf16* hi = g_Ehi + row * (long)S_LEN;
    const bf16* lo = g_Elo + row * (long)S_LEN;
    float* w = W + row * (long)S_LEN;
    for (int i = threadIdx.x * 8; i < S_LEN; i += 256 * 8) {
        uint4 h4 = *(const uint4*)(hi + i);
        uint4 l4 = *(const uint4*)(lo + i);
        const uint32_t hh[4] = {h4.x, h4.y, h4.z, h4.w};
        const uint32_t ll[4] = {l4.x, l4.y, l4.z, l4.w};
        float o[8];
#pragma unroll
        for (int j = 0; j < 4; j++) {
            __nv_bfloat162 hb = *(const __nv_bfloat162*)&hh[j];
            __nv_bfloat162 lb = *(const __nv_bfloat162*)&ll[j];
            o[j * 2 + 0] = (__bfloat162float(hb.x) + __bfloat162float(lb.x)) * inv;
            o[j * 2 + 1] = (__bfloat162float(hb.y) + __bfloat162float(lb.y)) * inv;
        }
        *(float4*)(w + i)     = make_float4(o[0], o[1], o[2], o[3]);
        *(float4*)(w + i + 4) = make_float4(o[4], o[5], o[6], o[7]);
    }
}

// ---------------------------------------------------------------------------
// Launch
// ---------------------------------------------------------------------------
extern "C" void kernel_launch(void* const* d_in, const int* in_sizes, int n_in,
                              void* d_out, int out_size) {
    const float* hidden = (const float*)d_in[0];
    const float* cosp   = (const float*)d_in[1];
    const float* sinp   = (const float*)d_in[2];
    const float* w[4]   = {(const float*)d_in[3], (const float*)d_in[4],
                           (const float*)d_in[5], (const float*)d_in[6]};

    float* out    = (float*)d_out;
    float* attn_w = out + (long)S_LEN * E_DIM;

    float* qkv; cudaGetSymbolAddress((void**)&qkv, g_qkv);
    bf16 *Hhi, *Hlo, *Whi, *Wlo, *Qhi, *Qlo, *Khi, *Klo, *Vthi, *Vtlo, *Ehi, *Elo, *AOhi, *AOlo;
    float *part, *isum;
    cudaGetSymbolAddress((void**)&Hhi, g_Hhi);  cudaGetSymbolAddress((void**)&Hlo, g_Hlo);
    cudaGetSymbolAddress((void**)&Whi, g_Whi);  cudaGetSymbolAddress((void**)&Wlo, g_Wlo);
    cudaGetSymbolAddress((void**)&Qhi, g_Qhi);  cudaGetSymbolAddress((void**)&Qlo, g_Qlo);
    cudaGetSymbolAddress((void**)&Khi, g_Khi);  cudaGetSymbolAddress((void**)&Klo, g_Klo);
    cudaGetSymbolAddress((void**)&Vthi, g_Vthi); cudaGetSymbolAddress((void**)&Vtlo, g_Vtlo);
    cudaGetSymbolAddress((void**)&Ehi, g_Ehi);  cudaGetSymbolAddress((void**)&Elo, g_Elo);
    cudaGetSymbolAddress((void**)&AOhi, g_AOhi); cudaGetSymbolAddress((void**)&AOlo, g_AOlo);
    cudaGetSymbolAddress((void**)&part, g_part); cudaGetSymbolAddress((void**)&isum, g_isum);

    const int SMEM128 = 3 * (2 * 128 * 80 + 2 * 128 * 80);  // 122880
    const int SMEM64  = 3 * (2 * 128 * 80 + 2 * 64 * 80);   // 92160
    cudaFuncSetAttribute(mma_gemm<128, 0>, cudaFuncAttributeMaxDynamicSharedMemorySize, SMEM128);
    cudaFuncSetAttribute(mma_gemm<128, 1>, cudaFuncAttributeMaxDynamicSharedMemorySize, SMEM128);
    cudaFuncSetAttribute(mma_gemm<128, 3>, cudaFuncAttributeMaxDynamicSharedMemorySize, SMEM128);
    cudaFuncSetAttribute(mma_gemm<64, 2>,  cudaFuncAttributeMaxDynamicSharedMemorySize, SMEM64);

    // 1) bf16 splits of hidden + weights
    {
        long n = (long)S_LEN * E_DIM;
        split_kernel<<<(int)((n / 4 + 255) / 256), 256>>>(hidden, Hhi, Hlo, n);
        long nw = (long)E_DIM * E_DIM;
        for (int i = 0; i < 4; i++)
            split_kernel<<<(int)((nw / 4 + 255) / 256), 256>>>(w[i], Whi + (long)i * nw, Wlo + (long)i * nw, nw);
    }

    // 2) QKV projections, batched over z={q,k,v} (head-major fp32)
    {
        dim3 g(E_DIM / 128, (S_LEN + 127) / 128, 3);
        mma_gemm<128, 1><<<g, 256, SMEM128>>>(Hhi, Hlo, E_DIM, 0,
                                              Whi, Wlo, E_DIM, (long)E_DIM * E_DIM,
                                              qkv, 0, 0, nullptr, nullptr, nullptr, nullptr,
                                              32, S_LEN, E_DIM);
    }

    // 3) RoPE + split (1/sqrt(D) folded into Q); V transpose + split
    {
        long total = (long)H_NUM * S_LEN * 32;
        const long HSD = (long)H_NUM * S_LEN * D_DIM;
        rope_split_kernel<<<(int)((total + 255) / 256), 256>>>(qkv, qkv + HSD, cosp, sinp);
        dim3 gv(S_LEN / 64, 1, H_NUM);
        vtrans_kernel<<<gv, 256>>>(qkv + 2 * HSD);
    }

    // 4) score GEMM: E = exp(Q K^T / 8) (bf16 splits) + partial row sums
    {
        dim3 g((S_LEN + 127) / 128, (S_LEN + 127) / 128, H_NUM);
        mma_gemm<128, 3><<<g, 256, SMEM128>>>(Qhi, Qlo, 64, (long)S_LEN * 64,
                                              Khi, Klo, 64, (long)S_LEN * 64,
                                              nullptr, 0, 0, Ehi, Elo, nullptr, part,
                                              2, S_LEN, S_LEN);
    }

    // 5) row sums -> inverse
    reduce_rowsum_kernel<<<(H_NUM * S_LEN + 255) / 256, 256>>>();

    // 6) attn_weights = E * invsum (fp32)
    normalize_kernel<<<H_NUM * S_LEN, 256>>>(attn_w);

    // 7) PV (unnormalized E, scaled epilogue) -> AO bf16 splits
    {
        dim3 g(1, (S_LEN + 127) / 128, H_NUM);
        mma_gemm<64, 2><<<g, 256, SMEM64>>>(Ehi, Elo, S_LEN, (long)S_LEN * S_LEN,
                                            Vthi, Vtlo, S_LEN, (long)64 * S_LEN,
                                            nullptr, 0, 0, AOhi, AOlo, isum, nullptr,
                                            98, S_LEN, 64);
    }

    // 8) out = AO Wo^T
    {
        dim3 g(E_DIM / 128, (S_LEN + 127) / 128, 1);
        long nw = (long)E_DIM * E_DIM;
        mma_gemm<128, 0><<<g, 256, SMEM128>>>(AOhi, AOlo, E_DIM, 0,
                                              Whi + 3 * nw, Wlo + 3 * nw, E_DIM, 0,
                                              out, E_DIM, 0, nullptr, nullptr, nullptr, nullptr,
                                              32, S_LEN, E_DIM);
    }
}

// round 5
// speedup vs baseline: 1.7193x; 1.7193x over previous
#include <cuda_runtime.h>
#include <cuda_bf16.h>
#include <math.h>
#include <stdint.h>

#define S_LEN 3136
#define E_DIM 1024
#define H_NUM 16
#define D_DIM 64
#define NTILES 25   // ceil(3136/128)

typedef __nv_bfloat16 bf16;

// ---------------------------------------------------------------------------
// Device scratch (allocation is forbidden)
// ---------------------------------------------------------------------------
__device__ float g_qkv[3][H_NUM * S_LEN * D_DIM];   // fp32 head-major q,k,v

__device__ __align__(16) bf16 g_Hhi[S_LEN * E_DIM];
__device__ __align__(16) bf16 g_Hlo[S_LEN * E_DIM];
__device__ __align__(16) bf16 g_Whi[4][E_DIM * E_DIM];
__device__ __align__(16) bf16 g_Wlo[4][E_DIM * E_DIM];
__device__ __align__(16) bf16 g_Qhi[H_NUM * S_LEN * D_DIM];
__device__ __align__(16) bf16 g_Qlo[H_NUM * S_LEN * D_DIM];
__device__ __align__(16) bf16 g_Khi[H_NUM * S_LEN * D_DIM];
__device__ __align__(16) bf16 g_Klo[H_NUM * S_LEN * D_DIM];
__device__ __align__(16) bf16 g_Vthi[H_NUM * D_DIM * S_LEN];   // [h][d][s]
__device__ __align__(16) bf16 g_Vtlo[H_NUM * D_DIM * S_LEN];
__device__ __align__(16) bf16 g_Ehi[(long)H_NUM * S_LEN * S_LEN];  // unnormalized exp
__device__ __align__(16) bf16 g_Elo[(long)H_NUM * S_LEN * S_LEN];
__device__ __align__(16) bf16 g_AOhi[S_LEN * E_DIM];
__device__ __align__(16) bf16 g_AOlo[S_LEN * E_DIM];
__device__ float g_part[NTILES * H_NUM * S_LEN];   // per-(ntile,row) partial sums
__device__ float g_isum[H_NUM * S_LEN];            // 1 / rowsum

// ---------------------------------------------------------------------------
// PTX helpers (sm_80-era: cp.async + ldmatrix + mma.sync)
// ---------------------------------------------------------------------------
__device__ __forceinline__ uint32_t smem_u32(const void* p) {
    uint32_t a;
    asm("{ .reg .u64 t; cvta.to.shared.u64 t, %1; cvt.u32.u64 %0, t; }" : "=r"(a) : "l"(p));
    return a;
}
__device__ __forceinline__ void cp16(uint32_t dst, const void* src, int srcsize) {
    asm volatile("cp.async.cg.shared.global [%0], [%1], 16, %2;"
                 :: "r"(dst), "l"(src), "r"(srcsize));
}
__device__ __forceinline__ void cpcommit() { asm volatile("cp.async.commit_group;"); }
template <int N> __device__ __forceinline__ void cpwait() {
    asm volatile("cp.async.wait_group %0;" :: "n"(N));
}
__device__ __forceinline__ void ldm4(uint32_t* r, uint32_t a) {
    asm volatile("ldmatrix.sync.aligned.m8n8.x4.shared.b16 {%0,%1,%2,%3}, [%4];"
                 : "=r"(r[0]), "=r"(r[1]), "=r"(r[2]), "=r"(r[3]) : "r"(a));
}
__device__ __forceinline__ void ldm2(uint32_t* r, uint32_t a) {
    asm volatile("ldmatrix.sync.aligned.m8n8.x2.shared.b16 {%0,%1}, [%2];"
                 : "=r"(r[0]), "=r"(r[1]) : "r"(a));
}
__device__ __forceinline__ void mma16816(float* d, const uint32_t* a, const uint32_t* b) {
    asm volatile("mma.sync.aligned.m16n8k16.row.col.f32.bf16.bf16.f32 "
                 "{%0,%1,%2,%3}, {%4,%5,%6,%7}, {%8,%9}, {%0,%1,%2,%3};"
                 : "+f"(d[0]), "+f"(d[1]), "+f"(d[2]), "+f"(d[3])
                 : "r"(a[0]), "r"(a[1]), "r"(a[2]), "r"(a[3]), "r"(b[0]), "r"(b[1]));
}
__device__ __forceinline__ void st_split2(bf16* hi, bf16* lo, float a, float b) {
    __nv_bfloat162 h;
    h.x = __float2bfloat16(a);
    h.y = __float2bfloat16(b);
    *(__nv_bfloat162*)hi = h;
    __nv_bfloat162 l;
    l.x = __float2bfloat16(a - __bfloat162float(h.x));
    l.y = __float2bfloat16(b - __bfloat162float(h.y));
    *(__nv_bfloat162*)lo = l;
}

// ---------------------------------------------------------------------------
// bf16x3 TN GEMM via mma.sync, 2-stage cp.async double buffer (R3-proven core)
//   A: bf16 hi/lo rows [M, K-contig] stride aRow;  B: bf16 hi/lo rows [N, K-contig]
// EPI 0: fp32 C[z*cBatch + m*ldc + n]
// EPI 1: fp32 head-major qkv: C[(z*H + (n>>6))*S*64 + m*64 + (n&63)]
// EPI 2: PV: AO bf16 split at [m*E + z*64 + n], scaled by invsum[z*S+m]
// EPI 3: score: e=exp(v); bf16 split E at [z*S*S + m*S + n]; partial row sums
//        via shfl reduction (few shared atomics)
// ---------------------------------------------------------------------------
template <int N_TILE, int EPI>
__global__ void __launch_bounds__(256, 1) mma_gemm(
    const bf16* __restrict__ Ahi, const bf16* __restrict__ Alo, long aRow, long aBatch,
    const bf16* __restrict__ Bhi, const bf16* __restrict__ Blo, long bRow, long bBatch,
    float* __restrict__ C, long ldc, long cBatch,
    bf16* __restrict__ Dhi, bf16* __restrict__ Dlo,
    const float* __restrict__ invsum, float* __restrict__ part,
    int kChunks, int M_valid, int N_valid) {

    constexpr int AST = 80;                 // smem bytes per 32-bf16 row (64 + 16 pad)
    constexpr int A_BYTES = 128 * AST;
    constexpr int B_BYTES = N_TILE * AST;
    constexpr int STAGE = 2 * A_BYTES + 2 * B_BYTES;

    extern __shared__ char smem[];
    const uint32_t sb = smem_u32(smem);
    __shared__ float s_red[128];

    const int tid = threadIdx.x;
    const int wid = tid >> 5, lane = tid & 31;
    constexpr int WC = (N_TILE == 128) ? 4 : 2;
    constexpr int WM = (N_TILE == 128) ? 64 : 32;
    constexpr int WN = 32;
    constexpr int MI = WM / 16, NI = WN / 8;
    const int warpM = (wid / WC) * WM;
    const int warpN = (wid % WC) * WN;

    const int mBase = blockIdx.y * 128;
    const int nBase = blockIdx.x * N_TILE;
    const int z = blockIdx.z;
    Ahi += aBatch * z; Alo += aBatch * z;
    Bhi += bBatch * z; Blo += bBatch * z;

    float acc[MI][NI][4];
#pragma unroll
    for (int i = 0; i < MI; i++)
#pragma unroll
        for (int j = 0; j < NI; j++)
#pragma unroll
            for (int q = 0; q < 4; q++) acc[i][j][q] = 0.0f;

    if (EPI == 3) {
        if (tid < 128) s_red[tid] = 0.0f;
    }

    auto issue_loads = [&](int c) {
        const long k0 = (long)c * 32;
        const uint32_t st = sb + (c & 1) * STAGE;
        for (int i = tid; i < 512; i += 256) {
            const int r = i >> 2, u = i & 3;
            const int row = mBase + r;
            const int ok = (row < M_valid) ? 16 : 0;
            const long srow = (row < M_valid) ? row : (M_valid - 1);
            const long off = srow * aRow + k0 + u * 8;
            const uint32_t dst = st + r * AST + u * 16;
            cp16(dst, Ahi + off, ok);
            cp16(dst + A_BYTES, Alo + off, ok);
        }
        for (int i = tid; i < N_TILE * 4; i += 256) {
            const int r = i >> 2, u = i & 3;
            const int row = nBase + r;
            const int ok = (row < N_valid) ? 16 : 0;
            const long srow = (row < N_valid) ? row : (N_valid - 1);
            const long off = srow * bRow + k0 + u * 8;
            const uint32_t dst = st + 2 * A_BYTES + r * AST + u * 16;
            cp16(dst, Bhi + off, ok);
            cp16(dst + B_BYTES, Blo + off, ok);
        }
        cpcommit();
    };

    issue_loads(0);

    for (int c = 0; c < kChunks; c++) {
        if (c + 1 < kChunks) { issue_loads(c + 1); cpwait<1>(); }
        else                 { cpwait<0>(); }
        __syncthreads();

        const uint32_t st = sb + (c & 1) * STAGE;
        const uint32_t aH = st, aL = st + A_BYTES;
        const uint32_t bH = st + 2 * A_BYTES, bL = bH + B_BYTES;

#pragma unroll
        for (int s = 0; s < 2; s++) {
            uint32_t aHf[MI][4], aLf[MI][4], bHf[NI][2], bLf[NI][2];
            const int arow = warpM + (lane & 15);
            const uint32_t acol = s * 32 + (lane >> 4) * 16;
#pragma unroll
            for (int mi = 0; mi < MI; mi++) {
                const uint32_t ao = (uint32_t)((arow + mi * 16) * AST) + acol;
                ldm4(aHf[mi], aH + ao);
                ldm4(aLf[mi], aL + ao);
            }
            const int l16 = lane & 15;
            const int brow = warpN + (l16 & 7);
            const uint32_t bcol = s * 32 + (l16 >> 3) * 16;
#pragma unroll
            for (int ni = 0; ni < NI; ni++) {
                const uint32_t bo = (uint32_t)((brow + ni * 8) * AST) + bcol;
                ldm2(bHf[ni], bH + bo);
                ldm2(bLf[ni], bL + bo);
            }
#pragma unroll
            for (int mi = 0; mi < MI; mi++)
#pragma unroll
                for (int ni = 0; ni < NI; ni++) {
                    mma16816(acc[mi][ni], aHf[mi], bHf[ni]);
                    mma16816(acc[mi][ni], aHf[mi], bLf[ni]);
                    mma16816(acc[mi][ni], aLf[mi], bHf[ni]);
                }
        }
        __syncthreads();
    }

    // ---------------- epilogue ----------------
    if (EPI == 3) {
        // exp + store E splits + row partial sums (shfl-reduced)
#pragma unroll
        for (int mi = 0; mi < MI; mi++) {
#pragma unroll
            for (int h = 0; h < 2; h++) {
                const int rl = warpM + mi * 16 + (lane >> 2) + h * 8;
                const int row = mBase + rl;
                const bool rok = (row < M_valid);
                float rsum = 0.0f;
#pragma unroll
                for (int ni = 0; ni < NI; ni++) {
                    const int col0 = nBase + warpN + ni * 8 + (lane & 3) * 2;
                    float e0 = 0.f, e1 = 0.f;
                    if (rok && col0 < N_valid) {
                        e0 = __expf(acc[mi][ni][h * 2 + 0]);
                        e1 = __expf(acc[mi][ni][h * 2 + 1]);
                        const long o = (long)z * S_LEN * S_LEN + (long)row * S_LEN + col0;
                        st_split2(Dhi + o, Dlo + o, e0, e1);
                    }
                    rsum += e0 + e1;
                }
                // reduce over the 4 lanes holding this row's columns
                rsum += __shfl_xor_sync(0xFFFFFFFFu, rsum, 1);
                rsum += __shfl_xor_sync(0xFFFFFFFFu, rsum, 2);
                if ((lane & 3) == 0 && rok) atomicAdd(&s_red[rl], rsum);
            }
        }
        __syncthreads();
        if (tid < 128) {
            const int row = mBase + tid;
            if (row < M_valid)
                part[(long)blockIdx.x * (H_NUM * S_LEN) + (long)z * S_LEN + row] = s_red[tid];
        }
        return;
    }

#pragma unroll
    for (int mi = 0; mi < MI; mi++) {
#pragma unroll
        for (int ni = 0; ni < NI; ni++) {
            const int rl0 = warpM + mi * 16 + (lane >> 2);
            const int col0 = nBase + warpN + ni * 8 + (lane & 3) * 2;
#pragma unroll
            for (int h = 0; h < 2; h++) {
                const int row = mBase + rl0 + h * 8;
                if (row >= M_valid) continue;
                const float v0 = acc[mi][ni][h * 2 + 0];
                const float v1 = acc[mi][ni][h * 2 + 1];
                if (EPI == 0) {
                    if (col0 < N_valid) {
                        C[(long)z * cBatch + (long)row * ldc + col0] = v0;
                        C[(long)z * cBatch + (long)row * ldc + col0 + 1] = v1;
                    }
                } else if (EPI == 1) {
                    const long o0 = ((long)z * H_NUM + (col0 >> 6)) * S_LEN * 64 + (long)row * 64 + (col0 & 63);
                    C[o0] = v0;
                    C[o0 + 1] = v1;
                } else if (EPI == 2) {
                    const float sc = invsum[(long)z * S_LEN + row];
                    const long o = (long)row * E_DIM + (long)z * 64 + col0;
                    st_split2(Dhi + o, Dlo + o, v0 * sc, v1 * sc);
                }
            }
        }
    }
}

// ---------------------------------------------------------------------------
// Small kernels
// ---------------------------------------------------------------------------
__global__ void split_kernel(const float* __restrict__ src, bf16* __restrict__ hi,
                             bf16* __restrict__ lo, long n) {
    long i = ((long)blockIdx.x * blockDim.x + threadIdx.x) * 4;
    if (i >= n) return;
    float4 v = *(const float4*)(src + i);
    float f[4] = {v.x, v.y, v.z, v.w};
#pragma unroll
    for (int j = 0; j < 4; j++) {
        bf16 h = __float2bfloat16(f[j]);
        hi[i + j] = h;
        lo[i + j] = __float2bfloat16(f[j] - __bfloat162float(h));
    }
}

__global__ void rope_split_kernel(const float* __restrict__ Q, const float* __restrict__ K,
                                  const float* __restrict__ cosp, const float* __restrict__ sinp) {
    const long total = (long)H_NUM * S_LEN * 32;
    long idx = (long)blockIdx.x * blockDim.x + threadIdx.x;
    if (idx >= total) return;
    const int d = (int)(idx & 31);
    const long hs = idx >> 5;
    const int s = (int)(hs % S_LEN);
    const long base = hs << 6;

    const float c1 = cosp[s * 64 + d], s1 = sinp[s * 64 + d];
    const float c2 = cosp[s * 64 + d + 32], s2 = sinp[s * 64 + d + 32];

    float q1 = Q[base + d], q2 = Q[base + d + 32];
    float qa = (q1 * c1 - q2 * s1) * 0.125f;
    float qb = (q2 * c2 + q1 * s2) * 0.125f;
    float k1 = K[base + d], k2 = K[base + d + 32];
    float ka = k1 * c1 - k2 * s1;
    float kb = k2 * c2 + k1 * s2;

    bf16 h;
    h = __float2bfloat16(qa); g_Qhi[base + d] = h; g_Qlo[base + d] = __float2bfloat16(qa - __bfloat162float(h));
    h = __float2bfloat16(qb); g_Qhi[base + d + 32] = h; g_Qlo[base + d + 32] = __float2bfloat16(qb - __bfloat162float(h));
    h = __float2bfloat16(ka); g_Khi[base + d] = h; g_Klo[base + d] = __float2bfloat16(ka - __bfloat162float(h));
    h = __float2bfloat16(kb); g_Khi[base + d + 32] = h; g_Klo[base + d + 32] = __float2bfloat16(kb - __bfloat162float(h));
}

__global__ void vtrans_kernel(const float* __restrict__ V) {
    __shared__ float tile[64][65];
    const int h = blockIdx.z;
    const int s0 = blockIdx.x * 64;
    const int t = threadIdx.x;
    for (int i = t; i < 4096; i += 256) {
        int s = i >> 6, d = i & 63;
        tile[s][d] = V[((long)h * S_LEN + s0 + s) * 64 + d];
    }
    __syncthreads();
    for (int i = t; i < 4096; i += 256) {
        int d = i >> 6, s = i & 63;
        float v = tile[s][d];
        bf16 hi = __float2bfloat16(v);
        long o = ((long)h * 64 + d) * S_LEN + s0 + s;
        g_Vthi[o] = hi;
        g_Vtlo[o] = __float2bfloat16(v - __bfloat162float(hi));
    }
}

__global__ void reduce_rowsum_kernel() {
    int i = blockIdx.x * blockDim.x + threadIdx.x;
    if (i >= H_NUM * S_LEN) return;
    float s = 0.f;
#pragma unroll
    for (int t = 0; t < NTILES; t++) s += g_part[t * (H_NUM * S_LEN) + i];
    g_isum[i] = 1.0f / s;
}

// one block per attention row: attn_w = (Ehi + Elo) * invsum
__global__ void normalize_kernel(float* __restrict__ W) {
    const long row = blockIdx.x;
    const float inv = g_isum[row];
    const bf16* hi = g_Ehi + row * (long)S_LEN;
    const bf16* lo = g_Elo + row * (long)S_LEN;
    float* w = W + row * (long)S_LEN;
    for (int i = threadIdx.x * 8; i < S_LEN; i += 256 * 8) {
        uint4 h4 = *(const uint4*)(hi + i);
        uint4 l4 = *(const uint4*)(lo + i);
        const uint32_t hh[4] = {h4.x, h4.y, h4.z, h4.w};
        const uint32_t ll[4] = {l4.x, l4.y, l4.z, l4.w};
        float o[8];
#pragma unroll
        for (int j = 0; j < 4; j++) {
            __nv_bfloat162 hb = *(const __nv_bfloat162*)&hh[j];
            __nv_bfloat162 lb = *(const __nv_bfloat162*)&ll[j];
            o[j * 2 + 0] = (__bfloat162float(hb.x) + __bfloat162float(lb.x)) * inv;
            o[j * 2 + 1] = (__bfloat162float(hb.y) + __bfloat162float(lb.y)) * inv;
        }
        *(float4*)(w + i)     = make_float4(o[0], o[1], o[2], o[3]);
        *(float4*)(w + i + 4) = make_float4(o[4], o[5], o[6], o[7]);
    }
}

// ---------------------------------------------------------------------------
// Launch
// ---------------------------------------------------------------------------
extern "C" void kernel_launch(void* const* d_in, const int* in_sizes, int n_in,
                              void* d_out, int out_size) {
    const float* hidden = (const float*)d_in[0];
    const float* cosp   = (const float*)d_in[1];
    const float* sinp   = (const float*)d_in[2];
    const float* w[4]   = {(const float*)d_in[3], (const float*)d_in[4],
                           (const float*)d_in[5], (const float*)d_in[6]};

    float* out    = (float*)d_out;
    float* attn_w = out + (long)S_LEN * E_DIM;

    float* qkv; cudaGetSymbolAddress((void**)&qkv, g_qkv);
    bf16 *Hhi, *Hlo, *Whi, *Wlo, *Qhi, *Qlo, *Khi, *Klo, *Vthi, *Vtlo, *Ehi, *Elo, *AOhi, *AOlo;
    float *part, *isum;
    cudaGetSymbolAddress((void**)&Hhi, g_Hhi);  cudaGetSymbolAddress((void**)&Hlo, g_Hlo);
    cudaGetSymbolAddress((void**)&Whi, g_Whi);  cudaGetSymbolAddress((void**)&Wlo, g_Wlo);
    cudaGetSymbolAddress((void**)&Qhi, g_Qhi);  cudaGetSymbolAddress((void**)&Qlo, g_Qlo);
    cudaGetSymbolAddress((void**)&Khi, g_Khi);  cudaGetSymbolAddress((void**)&Klo, g_Klo);
    cudaGetSymbolAddress((void**)&Vthi, g_Vthi); cudaGetSymbolAddress((void**)&Vtlo, g_Vtlo);
    cudaGetSymbolAddress((void**)&Ehi, g_Ehi);  cudaGetSymbolAddress((void**)&Elo, g_Elo);
    cudaGetSymbolAddress((void**)&AOhi, g_AOhi); cudaGetSymbolAddress((void**)&AOlo, g_AOlo);
    cudaGetSymbolAddress((void**)&part, g_part); cudaGetSymbolAddress((void**)&isum, g_isum);

    const int SMEM128 = 2 * (2 * 128 * 80 + 2 * 128 * 80);  // 81920
    const int SMEM64  = 2 * (2 * 128 * 80 + 2 * 64 * 80);   // 61440
    cudaFuncSetAttribute(mma_gemm<128, 0>, cudaFuncAttributeMaxDynamicSharedMemorySize, SMEM128);
    cudaFuncSetAttribute(mma_gemm<128, 1>, cudaFuncAttributeMaxDynamicSharedMemorySize, SMEM128);
    cudaFuncSetAttribute(mma_gemm<128, 3>, cudaFuncAttributeMaxDynamicSharedMemorySize, SMEM128);
    cudaFuncSetAttribute(mma_gemm<64, 2>,  cudaFuncAttributeMaxDynamicSharedMemorySize, SMEM64);

    // 1) bf16 splits of hidden + weights
    {
        long n = (long)S_LEN * E_DIM;
        split_kernel<<<(int)((n / 4 + 255) / 256), 256>>>(hidden, Hhi, Hlo, n);
        long nw = (long)E_DIM * E_DIM;
        for (int i = 0; i < 4; i++)
            split_kernel<<<(int)((nw / 4 + 255) / 256), 256>>>(w[i], Whi + (long)i * nw, Wlo + (long)i * nw, nw);
    }

    // 2) QKV projections, batched over z={q,k,v} (head-major fp32)
    {
        dim3 g(E_DIM / 128, (S_LEN + 127) / 128, 3);
        mma_gemm<128, 1><<<g, 256, SMEM128>>>(Hhi, Hlo, E_DIM, 0,
                                              Whi, Wlo, E_DIM, (long)E_DIM * E_DIM,
                                              qkv, 0, 0, nullptr, nullptr, nullptr, nullptr,
                                              32, S_LEN, E_DIM);
    }

    // 3) RoPE + split (1/sqrt(D) folded into Q); V transpose + split
    {
        long total = (long)H_NUM * S_LEN * 32;
        const long HSD = (long)H_NUM * S_LEN * D_DIM;
        rope_split_kernel<<<(int)((total + 255) / 256), 256>>>(qkv, qkv + HSD, cosp, sinp);
        dim3 gv(S_LEN / 64, 1, H_NUM);
        vtrans_kernel<<<gv, 256>>>(qkv + 2 * HSD);
    }

    // 4) score GEMM: E = exp(Q K^T / 8) (bf16 splits) + partial row sums
    {
        dim3 g((S_LEN + 127) / 128, (S_LEN + 127) / 128, H_NUM);
        mma_gemm<128, 3><<<g, 256, SMEM128>>>(Qhi, Qlo, 64, (long)S_LEN * 64,
                                              Khi, Klo, 64, (long)S_LEN * 64,
                                              nullptr, 0, 0, Ehi, Elo, nullptr, part,
                                              2, S_LEN, S_LEN);
    }

    // 5) row sums -> inverse
    reduce_rowsum_kernel<<<(H_NUM * S_LEN + 255) / 256, 256>>>();

    // 6) attn_weights = E * invsum (fp32)
    normalize_kernel<<<H_NUM * S_LEN, 256>>>(attn_w);

    // 7) PV (unnormalized E, scaled epilogue) -> AO bf16 splits
    {
        dim3 g(1, (S_LEN + 127) / 128, H_NUM);
        mma_gemm<64, 2><<<g, 256, SMEM64>>>(Ehi, Elo, S_LEN, (long)S_LEN * S_LEN,
                                            Vthi, Vtlo, S_LEN, (long)64 * S_LEN,
                                            nullptr, 0, 0, AOhi, AOlo, isum, nullptr,
                                            98, S_LEN, 64);
    }

    // 8) out = AO Wo^T
    {
        dim3 g(E_DIM / 128, (S_LEN + 127) / 128, 1);
        long nw = (long)E_DIM * E_DIM;
        mma_gemm<128, 0><<<g, 256, SMEM128>>>(AOhi, AOlo, E_DIM, 0,
                                              Whi + 3 * nw, Wlo + 3 * nw, E_DIM, 0,
                                              out, E_DIM, 0, nullptr, nullptr, nullptr, nullptr,
                                              32, S_LEN, E_DIM);
    }
}